// round 3
// baseline (speedup 1.0000x reference)
#include <cuda_runtime.h>
#include <cuda_fp16.h>
#include <cstdint>

#define DEV_INLINE __device__ __forceinline__

static constexpr int NDIM   = 1024;   // DCT length (axis 1)
static constexpr int NBATCH = 32;

// GEMM tiling (portable mma.sync path — tcgen05 is rejected by the compute_103 PTX target)
static constexpr int BM = 128;        // DCT output rows per CTA
static constexpr int BN = 128;        // (b,m) columns per CTA
static constexpr int BK = 64;         // K per chunk (64 fp16 = 128 B = SW128 row)
static constexpr int NCHUNK = NDIM / BK;   // 16
static constexpr int STAGES = 3;
static constexpr int THREADS = 256;   // 8 warps: 2 (m) x 4 (n), warp tile 64x32

static constexpr int A_STAGE_BYTES = BM * 128;              // 16 KB (128 rows x 128B)
static constexpr int STAGE_BYTES   = 2 * A_STAGE_BYTES;     // 32 KB (A + B)
static constexpr int SMEM_TOTAL    = STAGES * STAGE_BYTES;  // 96 KB; also covers 128x132 f32 epilogue staging (67.6 KB)

// Scratch (allocation-free rule: __device__ globals)
__device__ __half d_C[NDIM * NDIM];                        // DCT matrix fp16, [k][j]
__device__ __half d_xt[(size_t)NBATCH * NDIM * NDIM];      // x transposed+fp16, [b][m][j]

// ---------------------------------------------------------------- helpers
DEV_INLINE uint32_t smem_u32(const void* p) {
    uint32_t a;
    asm("{ .reg .u64 t; cvta.to.shared.u64 t, %1; cvt.u32.u64 %0, t; }" : "=r"(a) : "l"(p));
    return a;
}
DEV_INLINE void cp16(uint32_t saddr, const void* g) {
    asm volatile("cp.async.cg.shared.global [%0], [%1], 16;" :: "r"(saddr), "l"(g));
}
DEV_INLINE void cp_commit() { asm volatile("cp.async.commit_group;"); }
template <int N> DEV_INLINE void cp_wait() { asm volatile("cp.async.wait_group %0;" :: "n"(N)); }
DEV_INLINE uint32_t swz(uint32_t off) { return off ^ ((off >> 3) & 0x70); }

DEV_INLINE void ldsm4(uint32_t* r, uint32_t addr) {
    asm volatile("ldmatrix.sync.aligned.m8n8.x4.shared.b16 {%0,%1,%2,%3}, [%4];"
                 : "=r"(r[0]), "=r"(r[1]), "=r"(r[2]), "=r"(r[3]) : "r"(addr));
}
DEV_INLINE void mma16816(float* c, const uint32_t* a, const uint32_t* b) {
    asm volatile(
        "mma.sync.aligned.m16n8k16.row.col.f32.f16.f16.f32 "
        "{%0,%1,%2,%3}, {%4,%5,%6,%7}, {%8,%9}, {%0,%1,%2,%3};"
        : "+f"(c[0]), "+f"(c[1]), "+f"(c[2]), "+f"(c[3])
        : "r"(a[0]), "r"(a[1]), "r"(a[2]), "r"(a[3]), "r"(b[0]), "r"(b[1]));
}

// ---------------------------------------------------------------- kernel 1: DCT matrix
__global__ void build_c_kernel() {
    int idx = blockIdx.x * 256 + threadIdx.x;       // 0 .. 2^20-1
    int k = idx >> 10;
    int j = idx & 1023;
    // angle = pi*(2j+1)*k/2048; reduce (2j+1)*k mod 4096 exactly in int so cosf stays accurate
    int t = (k * (2 * j + 1)) & 4095;
    float ang = (float)t * 1.5339807878856412e-3f;  // pi/2048
    float s = (k == 0) ? 0.03125f : 0.04419417382415922f;  // 1/32, sqrt(2)/32
    d_C[idx] = __float2half(s * cosf(ang));
}

// ---------------------------------------------------------------- kernel 2: transpose+fp16
// x[b][j][m] fp32 -> d_xt[b][m][j] fp16
__global__ void transpose_kernel(const float* __restrict__ x) {
    __shared__ float tile[32][33];
    int b = blockIdx.z;
    int m0 = blockIdx.x * 32, j0 = blockIdx.y * 32;
    const float* xb = x + ((size_t)b << 20);
    int tx = threadIdx.x, ty = threadIdx.y;
#pragma unroll
    for (int r = ty; r < 32; r += 8)
        tile[r][tx] = xb[(size_t)(j0 + r) * 1024 + m0 + tx];
    __syncthreads();
    __half* xtb = d_xt + ((size_t)b << 20);
#pragma unroll
    for (int r = ty; r < 32; r += 8)
        xtb[(size_t)(m0 + r) * 1024 + j0 + tx] = __float2half(tile[tx][r]);
}

// ---------------------------------------------------------------- kernel 3: GEMM
// Out[k, n] = sum_j C[k, j] * xt[n, j]    (n = b*1024 + m)
// A = d_C row-major K-contig; B = d_xt row-major K-contig (mma "col" operand).
DEV_INLINE void load_chunk(int q, int stage, int tid, int k0,
                           const __half* Bsrc, uint32_t sbase) {
    uint32_t abase = sbase + stage * STAGE_BYTES;
    uint32_t bbase = abase + A_STAGE_BYTES;
    int kc0 = q * BK;
    // A: 128 rows x 8 x 16B segs = 1024 segs; B: same
#pragma unroll
    for (int i = 0; i < 4; i++) {
        int s = tid + i * THREADS;
        int row = s >> 3, seg = s & 7;
        cp16(abase + swz((uint32_t)(row * 128 + seg * 16)),
             (const void*)(d_C + (size_t)(k0 + row) * NDIM + kc0 + seg * 8));
    }
#pragma unroll
    for (int i = 0; i < 4; i++) {
        int s = tid + i * THREADS;
        int row = s >> 3, seg = s & 7;
        cp16(bbase + swz((uint32_t)(row * 128 + seg * 16)),
             (const void*)(Bsrc + (size_t)row * NDIM + kc0 + seg * 8));
    }
}

__global__ void __launch_bounds__(THREADS, 2) dct_gemm_kernel(float* __restrict__ out) {
    extern __shared__ char smem[];
    uint32_t sbase = smem_u32(smem);
    int tid = threadIdx.x;
    int lane = tid & 31, wid = tid >> 5;
    int warp_m = wid & 1;         // 2 m-warps
    int warp_n = wid >> 1;        // 4 n-warps

    int k0 = blockIdx.x * BM;                   // DCT row tile
    int b  = blockIdx.y >> 3;                   // 1024/BN = 8 n-tiles per batch image
    int m0 = (blockIdx.y & 7) * BN;
    const __half* Bsrc = d_xt + ((size_t)b << 20) + (size_t)m0 * NDIM;

    float acc[4][4][4] = {};                    // [mi][ni][frag]

    // ldmatrix per-thread address components (tile = lane>>3, row-in-tile = lane&7)
    //   A frag tiles: (m+0/k+0), (m+8/k+0), (m+0/k+8), (m+8/k+8)
    int a_row = warp_m * 64 + (lane & 7) + (((lane >> 3) & 1) << 3);
    int a_kx  = (lane >> 4) << 3;
    //   B frag tiles: (n+0/k+0), (n+0/k+8), (n+8/k+0), (n+8/k+8)
    int b_row = warp_n * 32 + (lane & 7) + ((lane >> 4) << 3);
    int b_kx  = ((lane >> 3) & 1) << 3;

    // prologue
#pragma unroll
    for (int s = 0; s < STAGES - 1; s++) { load_chunk(s, s, tid, k0, Bsrc, sbase); cp_commit(); }

    for (int c = 0; c < NCHUNK; c++) {
        int q = c + STAGES - 1;
        if (q < NCHUNK) load_chunk(q, q % STAGES, tid, k0, Bsrc, sbase);
        cp_commit();                         // always commit (possibly empty group)
        cp_wait<STAGES - 1>();               // chunk c complete
        __syncthreads();

        uint32_t abase = sbase + (c % STAGES) * STAGE_BYTES;
        uint32_t bbase = abase + A_STAGE_BYTES;
#pragma unroll
        for (int ks = 0; ks < BK / 16; ks++) {
            uint32_t af[4][4];
#pragma unroll
            for (int mi = 0; mi < 4; mi++)
                ldsm4(af[mi], abase + swz((uint32_t)((a_row + mi * 16) * 128 +
                                                     (ks * 16 + a_kx) * 2)));
            uint32_t bf[4][2];
#pragma unroll
            for (int h = 0; h < 2; h++) {
                uint32_t r[4];
                ldsm4(r, bbase + swz((uint32_t)((b_row + h * 16) * 128 +
                                                (ks * 16 + b_kx) * 2)));
                bf[2 * h + 0][0] = r[0]; bf[2 * h + 0][1] = r[1];
                bf[2 * h + 1][0] = r[2]; bf[2 * h + 1][1] = r[3];
            }
#pragma unroll
            for (int mi = 0; mi < 4; mi++)
#pragma unroll
                for (int ni = 0; ni < 4; ni++)
                    mma16816(acc[mi][ni], af[mi], bf[ni]);
        }
        __syncthreads();                     // before next iter overwrites this stage
    }

    // epilogue: regs -> smem staging (stride 132) -> coalesced float4 stores
    float* stg = (float*)smem;
    int gr = lane >> 2, cl = (lane & 3) * 2;
#pragma unroll
    for (int mi = 0; mi < 4; mi++)
#pragma unroll
        for (int ni = 0; ni < 4; ni++) {
            int r0 = warp_m * 64 + mi * 16 + gr;
            int col = warp_n * 32 + ni * 8 + cl;
            stg[r0 * 132 + col]       = acc[mi][ni][0];
            stg[r0 * 132 + col + 1]   = acc[mi][ni][1];
            stg[(r0 + 8) * 132 + col]     = acc[mi][ni][2];
            stg[(r0 + 8) * 132 + col + 1] = acc[mi][ni][3];
        }
    __syncthreads();

    size_t ob = ((size_t)b << 20) + (size_t)k0 * 1024 + m0;
#pragma unroll
    for (int i = 0; i < 16; i++) {
        int idx = i * THREADS + tid;         // 4096 float4s = 128 rows x 32
        int row = idx >> 5;
        int c4 = (idx & 31) * 4;
        float4 v = *(const float4*)(stg + row * 132 + c4);
        *(float4*)(out + ob + (size_t)row * 1024 + c4) = v;
    }
}

// ---------------------------------------------------------------- launch
extern "C" void kernel_launch(void* const* d_in, const int* in_sizes, int n_in,
                              void* d_out, int out_size) {
    (void)in_sizes; (void)n_in; (void)out_size;
    const float* x = (const float*)d_in[0];
    float* out = (float*)d_out;

    build_c_kernel<<<(NDIM * NDIM) / 256, 256>>>();

    dim3 tg(32, 32, NBATCH), tb(32, 8);
    transpose_kernel<<<tg, tb>>>(x);

    cudaFuncSetAttribute(dct_gemm_kernel, cudaFuncAttributeMaxDynamicSharedMemorySize, SMEM_TOTAL);
    dim3 gg(NDIM / BM, (NBATCH * NDIM) / BN);   // (8, 256)
    dct_gemm_kernel<<<gg, THREADS, SMEM_TOTAL>>>(out);
}